// round 16
// baseline (speedup 1.0000x reference)
#include <cuda_runtime.h>
#include <cstdint>

// Problem shape (dataset-fixed, sizes read dynamically):
//   child_val:    (1, 2,000,000) float32   -> d_in[0]   (8MB, L2-resident)
//   flat_indices: (32,000,000,)  int32     -> d_in[1]
//   segment_ids:  (32,000,000,)  int32 sorted -> d_in[2]
//   out:          (1, 1,000,000) float32
//
// TERMINAL FORM. Segsum is at its structural floor: 0.94 L1tex
// wavefronts/cyc (94% of per-SM max) and ~95% of the L2 LTS sector cap,
// both funded by the problem's irreducible 32M scalar random gathers.
// Stable 120.7-121.4us (ncu) across R7-R15; end-to-end noise band
// 121.9-123.0us. This round: record config + 32-bit index arithmetic
// (E=32M << 2^31) — strictly-free ALU trim, identical memory behavior.
//
// Mechanisms: EPT=8 + launch_bounds(256,8) -> 64 warps/SM (L1tex queue
// full); warp-merged segmented-scan atomics (~1.3M REDG vs ~5M); .cg
// gathers (8MB table, ~97% L1 miss -> skip L1 allocate); .cs streamed
// reads + zero stores (read-once/evict-first -> table keeps L2 ways).
// Dead ends verified: persistent grid (R6), cudaMemsetAsync (R8),
// multi-store zero (R9), TPB=128 (R9/R10), PDL (R12), prologue TPB (R14).

static constexpr int EPT = 8;            // edges per thread
static constexpr int TPB = 256;          // threads per block
static constexpr unsigned FULL = 0xFFFFFFFFu;

__global__ void zero_out_kernel(float4* __restrict__ out, int n4) {
    int i = blockIdx.x * blockDim.x + threadIdx.x;
    if (i < n4)
        __stcs(out + i, make_float4(0.f, 0.f, 0.f, 0.f));  // evict-first
}

__global__ __launch_bounds__(TPB, 8) void segsum_kernel(
    const float* __restrict__ cv,
    const int*   __restrict__ fi,
    const int*   __restrict__ seg,
    float*       __restrict__ out,
    int E)
{
    const int lane = threadIdx.x & 31;
    const int warp_gid  = (blockIdx.x * TPB + threadIdx.x) >> 5;
    const int warp_base = warp_gid * (32 * EPT);          // < 2^25, no overflow
    if (warp_base >= E) return;

    if (warp_base + 32 * EPT <= E) {
        // ---- Full-warp fast path ----
        const int base = warp_base + lane * EPT;

        int4  i4[EPT / 4];
        int4  s4[EPT / 4];
        float v [EPT];

        // seg vectors first (independent; in flight under the gather chain).
        // .cs: read-once streams, evict-first -> keep L2 ways for the table.
        #pragma unroll
        for (int k = 0; k < EPT / 4; k++)
            s4[k] = __ldcs(reinterpret_cast<const int4*>(seg + base + 4 * k));

        #pragma unroll
        for (int k = 0; k < EPT / 4; k++)
            i4[k] = __ldcs(reinterpret_cast<const int4*>(fi + base + 4 * k));

        // Gathers: L2-only (.cg) — 8MB table, ~97% L1 miss.
        #pragma unroll
        for (int k = 0; k < EPT / 4; k++) {
            v[4 * k + 0] = __ldcg(cv + i4[k].x);
            v[4 * k + 1] = __ldcg(cv + i4[k].y);
            v[4 * k + 2] = __ldcg(cv + i4[k].z);
            v[4 * k + 3] = __ldcg(cv + i4[k].w);
        }

        int se[EPT];
        #pragma unroll
        for (int k = 0; k < EPT / 4; k++) {
            se[4 * k + 0] = s4[k].x; se[4 * k + 1] = s4[k].y;
            se[4 * k + 2] = s4[k].z; se[4 * k + 3] = s4[k].w;
        }

        // Per-thread run-length pass: head run, interior atomics, tail run.
        int   hs = se[0];  float ha = 0.f;
        bool  multi = false;
        int   cur = se[0]; float acc = v[0];
        #pragma unroll
        for (int e = 1; e < EPT; e++) {
            if (se[e] != cur) {
                if (!multi) { hs = cur; ha = acc; multi = true; }
                else        { atomicAdd(out + cur, acc); }   // interior (rare)
                cur = se[e];
                acc = v[e];
            } else {
                acc += v[e];
            }
        }
        const int   ts = cur;
        const float ta = acc;

        // ---- Warp merge ----
        const int myhead = multi ? hs : ts;
        const int ts_prev = __shfl_up_sync(FULL, ts, 1);
        const bool conn = (lane > 0) && (myhead == ts_prev);

        // Segmented inclusive scan over tail partials.
        float c = ta;
        int   hflag = !(conn && !multi);
        #pragma unroll
        for (int d = 1; d < 32; d <<= 1) {
            float c_up = __shfl_up_sync(FULL, c, d);
            int   h_up = __shfl_up_sync(FULL, hflag, d);
            if (lane >= d) {
                if (!hflag) c += c_up;
                hflag |= h_up;
            }
        }

        const float cprev    = __shfl_up_sync(FULL, c, 1);
        const int   conn_nxt = __shfl_down_sync(FULL, (int)conn, 1);

        if (multi)
            atomicAdd(out + hs, conn ? (ha + cprev) : ha);

        if (lane == 31 || !conn_nxt)
            atomicAdd(out + ts, c);
    } else {
        // ---- Tail path: per-lane scalar, bounds-checked, direct atomics ----
        const int base = warp_base + lane * EPT;
        if (base >= E) return;
        const int end = base + EPT < E ? base + EPT : E;
        int   cur = -1;
        float acc = 0.f;
        for (int e = base; e < end; e++) {
            int s = seg[e];
            float val = __ldcg(cv + fi[e]);
            if (s != cur) {
                if (cur >= 0) atomicAdd(out + cur, acc);
                cur = s;
                acc = val;
            } else {
                acc += val;
            }
        }
        if (cur >= 0) atomicAdd(out + cur, acc);
    }
}

extern "C" void kernel_launch(void* const* d_in, const int* in_sizes, int n_in,
                              void* d_out, int out_size) {
    const float* cv  = (const float*)d_in[0];
    const int*   fi  = (const int*)d_in[1];
    const int*   seg = (const int*)d_in[2];
    float*       out = (float*)d_out;

    int E = in_sizes[1];
    int N = out_size;

    // Zero output (harness poisons to 0xAA; empty segments must read 0).
    {
        int n4 = N / 4;
        int blocks = (n4 + TPB - 1) / TPB;
        zero_out_kernel<<<blocks, TPB>>>((float4*)out, n4);
    }

    int threads_needed = (E + EPT - 1) / EPT;
    int blocks = (threads_needed + TPB - 1) / TPB;
    segsum_kernel<<<blocks, TPB>>>(cv, fi, seg, out, E);
}

// round 17
// speedup vs baseline: 1.0575x; 1.0575x over previous
#include <cuda_runtime.h>
#include <cstdint>

// Problem shape (dataset-fixed, sizes read dynamically):
//   child_val:    (1, 2,000,000) float32   -> d_in[0]   (8MB, L2-resident)
//   flat_indices: (32,000,000,)  int32     -> d_in[1]
//   segment_ids:  (32,000,000,)  int32 sorted -> d_in[2]
//   out:          (1, 1,000,000) float32
//
// TERMINAL FORM (exact R15 source — the proven-fastest SASS).
// Segsum: 120.7-120.9us in every run of this source; structural floor =
// 0.94 L1tex wavefronts/cyc (94% of per-SM max) + ~95% of the L2 LTS
// sector cap, both funded by the irreducible 32M scalar random gathers.
//
// IMPORTANT: keep 64-bit (long long) index arithmetic. R16 proved that
// switching to 32-bit regresses segsum by 6.3us — ptxas re-schedules the
// load batch and degrades the MLP grouping that saturates both memory
// pipes (L2 79.9->76.0%). Any SASS perturbation at this saturation point
// is a risk; this source is the validated optimum.
//
// Mechanisms: EPT=8 + launch_bounds(256,8) -> 64 warps/SM; warp-merged
// segmented-scan atomics (~1.3M REDG vs ~5M); .cg gathers (skip L1
// allocate on ~97%-miss loads); .cs streamed reads + zero stores.
// Dead ends verified: persistent grid (R6), cudaMemsetAsync (R8),
// multi-store zero (R9), TPB=128 (R9/R10), PDL (R12), prologue TPB (R14),
// 32-bit indices (R16).

static constexpr int EPT = 8;            // edges per thread
static constexpr int TPB = 256;          // threads per block
static constexpr unsigned FULL = 0xFFFFFFFFu;

__global__ void zero_out_kernel(float4* __restrict__ out, int n4) {
    int i = blockIdx.x * blockDim.x + threadIdx.x;
    if (i < n4)
        __stcs(out + i, make_float4(0.f, 0.f, 0.f, 0.f));  // evict-first
}

__global__ __launch_bounds__(TPB, 8) void segsum_kernel(
    const float* __restrict__ cv,
    const int*   __restrict__ fi,
    const int*   __restrict__ seg,
    float*       __restrict__ out,
    long long E)
{
    const int lane = threadIdx.x & 31;
    long long warp_gid  = ((long long)blockIdx.x * TPB + threadIdx.x) >> 5;
    long long warp_base = warp_gid * 32 * EPT;
    if (warp_base >= E) return;

    if (warp_base + 32 * EPT <= E) {
        // ---- Full-warp fast path ----
        long long base = warp_base + (long long)lane * EPT;

        int4  i4[EPT / 4];
        int4  s4[EPT / 4];
        float v [EPT];

        // seg vectors first (independent; in flight under the gather chain).
        // .cs: read-once streams, evict-first -> keep L2 ways for the table.
        #pragma unroll
        for (int k = 0; k < EPT / 4; k++)
            s4[k] = __ldcs(reinterpret_cast<const int4*>(seg + base + 4 * k));

        #pragma unroll
        for (int k = 0; k < EPT / 4; k++)
            i4[k] = __ldcs(reinterpret_cast<const int4*>(fi + base + 4 * k));

        // Gathers: L2-only (.cg) — 8MB table, ~97% L1 miss.
        #pragma unroll
        for (int k = 0; k < EPT / 4; k++) {
            v[4 * k + 0] = __ldcg(cv + i4[k].x);
            v[4 * k + 1] = __ldcg(cv + i4[k].y);
            v[4 * k + 2] = __ldcg(cv + i4[k].z);
            v[4 * k + 3] = __ldcg(cv + i4[k].w);
        }

        int se[EPT];
        #pragma unroll
        for (int k = 0; k < EPT / 4; k++) {
            se[4 * k + 0] = s4[k].x; se[4 * k + 1] = s4[k].y;
            se[4 * k + 2] = s4[k].z; se[4 * k + 3] = s4[k].w;
        }

        // Per-thread run-length pass: head run, interior atomics, tail run.
        int   hs = se[0];  float ha = 0.f;
        bool  multi = false;
        int   cur = se[0]; float acc = v[0];
        #pragma unroll
        for (int e = 1; e < EPT; e++) {
            if (se[e] != cur) {
                if (!multi) { hs = cur; ha = acc; multi = true; }
                else        { atomicAdd(out + cur, acc); }   // interior (rare)
                cur = se[e];
                acc = v[e];
            } else {
                acc += v[e];
            }
        }
        const int   ts = cur;
        const float ta = acc;

        // ---- Warp merge ----
        const int myhead = multi ? hs : ts;
        const int ts_prev = __shfl_up_sync(FULL, ts, 1);
        const bool conn = (lane > 0) && (myhead == ts_prev);

        // Segmented inclusive scan over tail partials.
        float c = ta;
        int   hflag = !(conn && !multi);
        #pragma unroll
        for (int d = 1; d < 32; d <<= 1) {
            float c_up = __shfl_up_sync(FULL, c, d);
            int   h_up = __shfl_up_sync(FULL, hflag, d);
            if (lane >= d) {
                if (!hflag) c += c_up;
                hflag |= h_up;
            }
        }

        const float cprev    = __shfl_up_sync(FULL, c, 1);
        const int   conn_nxt = __shfl_down_sync(FULL, (int)conn, 1);

        if (multi)
            atomicAdd(out + hs, conn ? (ha + cprev) : ha);

        if (lane == 31 || !conn_nxt)
            atomicAdd(out + ts, c);
    } else {
        // ---- Tail path: per-lane scalar, bounds-checked, direct atomics ----
        long long base = warp_base + (long long)lane * EPT;
        if (base >= E) return;
        long long end = base + EPT < E ? base + EPT : E;
        int   cur = -1;
        float acc = 0.f;
        for (long long e = base; e < end; e++) {
            int s = seg[e];
            float val = __ldcg(cv + fi[e]);
            if (s != cur) {
                if (cur >= 0) atomicAdd(out + cur, acc);
                cur = s;
                acc = val;
            } else {
                acc += val;
            }
        }
        if (cur >= 0) atomicAdd(out + cur, acc);
    }
}

extern "C" void kernel_launch(void* const* d_in, const int* in_sizes, int n_in,
                              void* d_out, int out_size) {
    const float* cv  = (const float*)d_in[0];
    const int*   fi  = (const int*)d_in[1];
    const int*   seg = (const int*)d_in[2];
    float*       out = (float*)d_out;

    long long E = (long long)in_sizes[1];
    int N = out_size;

    // Zero output (harness poisons to 0xAA; empty segments must read 0).
    {
        int n4 = N / 4;
        int blocks = (n4 + TPB - 1) / TPB;
        zero_out_kernel<<<blocks, TPB>>>((float4*)out, n4);
    }

    long long threads_needed = (E + EPT - 1) / EPT;
    int blocks = (int)((threads_needed + TPB - 1) / TPB);
    segsum_kernel<<<blocks, TPB>>>(cv, fi, seg, out, E);
}